// round 4
// baseline (speedup 1.0000x reference)
#include <cuda_runtime.h>
#include <math.h>

// Problem constants
#define BB   4
#define CIN  32
#define CH   64
#define HH   24
#define WW   24
#define HWN  576          // 24*24
#define TT   5
#define DK   32
#define DV   32
#define NHN  4
#define GG   4
#define HEADS 64          // B*G*NH
#define TKEYS 2880        // T*HW
#define KC    8           // key chunks
#define KPC   360         // keys per chunk

typedef unsigned long long ull;

// ---------------- f32x2 helpers (sm_100+) ------------------------------------
__device__ __forceinline__ ull pack2(float lo, float hi) {
    ull r; asm("mov.b64 %0,{%1,%2};" : "=l"(r) : "f"(lo), "f"(hi)); return r;
}
__device__ __forceinline__ void unpack2(ull v, float& lo, float& hi) {
    asm("mov.b64 {%0,%1},%2;" : "=f"(lo), "=f"(hi) : "l"(v));
}
__device__ __forceinline__ ull ffma2(ull a, ull b, ull c) {
    ull d; asm("fma.rn.f32x2 %0,%1,%2,%3;" : "=l"(d) : "l"(a), "l"(b), "l"(c)); return d;
}
__device__ __forceinline__ ull fmul2(ull a, ull b) {
    ull d; asm("mul.rn.f32x2 %0,%1,%2;" : "=l"(d) : "l"(a), "l"(b)); return d;
}
__device__ __forceinline__ float ex2f(float x) {
    float r; asm("ex2.approx.ftz.f32 %0,%1;" : "=f"(r) : "f"(x)); return r;
}

// ---------------- scratch (device globals; no allocation allowed) -------------
__device__ float  g_xg[BB*GG*CH*HWN];        // conv on inputs, 4 gates x 64 ch
__device__ float  g_co[BB*GG*(CH-DV)*HWN];   // conv on rep, 4 gates x 32 ch
__device__ float4 g_q[HEADS*HWN*2];          // Q [head][q][8] (scaled by log2e/sqrt8)
__device__ float  g_K2[HEADS*TKEYS*16];      // K duplicated: [head][j][(k0,k0,k1,k1,...)]
__device__ float4 g_V[HEADS*TKEYS*2];        // V [head][j][8]
__device__ float  g_L[KC*HEADS*HWN];         // partial exp-sums
__device__ float4 g_A[KC*HEADS*HWN*2];       // partial weighted V sums
__device__ float  g_attnp[BB*GG*DV*HWN];     // projected attention

// =============================================================================
// Front fat kernel: conv_rep | conv_x | kv | q, dispatched by blockIdx.x.
// 288 threads/block everywhere.
// =============================================================================

// ---- conv body: 4 gates per thread, 2 pixels per thread ---------------------
template<int IC, int OC, int WHICH>
__device__ __forceinline__
void conv_body(const float* __restrict__ in,   // [B][IC][24][24]
               const float* __restrict__ w,    // [G][OC][IC][3][3]
               const float* __restrict__ bias, // [G][OC]
               int idx, float* sm)
{
    const int b  = idx & 3;
    const int oc = idx >> 2;
    const int tid = threadIdx.x;

    for (int i = tid; i < GG*IC*9; i += 288) {
        int g = i / (IC*9);
        int r = i - g*(IC*9);
        sm[i] = w[(g*OC + oc)*IC*9 + r];
    }
    __syncthreads();

    const int p0 = tid, p1 = tid + 288;
    const int y0 = p0 / WW, x0 = p0 % WW;
    const int y1 = p1 / WW, x1 = p1 % WW;

    float acc0[GG], acc1[GG];
    #pragma unroll
    for (int g = 0; g < GG; g++) {
        float bv = __ldg(bias + g*OC + oc);
        acc0[g] = bv; acc1[g] = bv;
    }

    for (int ic = 0; ic < IC; ic++) {
        const float* ip = in + (b*IC + ic)*HWN;
        float v0[9], v1[9];
        #pragma unroll
        for (int ky = 0; ky < 3; ky++) {
            #pragma unroll
            for (int kx = 0; kx < 3; kx++) {
                int iy = y0 + ky - 1, ix = x0 + kx - 1;
                v0[ky*3+kx] = (iy >= 0 && iy < HH && ix >= 0 && ix < WW)
                              ? __ldg(ip + iy*WW + ix) : 0.f;
                int jy = y1 + ky - 1, jx = x1 + kx - 1;
                v1[ky*3+kx] = (jy >= 0 && jy < HH && jx >= 0 && jx < WW)
                              ? __ldg(ip + jy*WW + jx) : 0.f;
            }
        }
        #pragma unroll
        for (int g = 0; g < GG; g++) {
            const float* wp = &sm[(g*IC + ic)*9];
            #pragma unroll
            for (int kk = 0; kk < 9; kk++) {
                float wv = wp[kk];
                acc0[g] = fmaf(v0[kk], wv, acc0[g]);
                acc1[g] = fmaf(v1[kk], wv, acc1[g]);
            }
        }
    }
    float* out = (WHICH == 0) ? g_xg : g_co;
    #pragma unroll
    for (int g = 0; g < GG; g++) {
        out[((b*GG + g)*OC + oc)*HWN + p0] = acc0[g];
        out[((b*GG + g)*OC + oc)*HWN + p1] = acc1[g];
    }
}

// ---- kv body: f32x2 pixel-paired micro-GEMM, 8 outputs x 4 px per thread ----
__device__ __forceinline__
void kv_body(const float* __restrict__ hist, // [B][T][CH][HW]
             const float* __restrict__ kvw,  // [G][DK+DV][CH]
             const float* __restrict__ kvb,  // [G][DK+DV]
             int r, float* sm)
{
    // r in [0, 320): half = r&1, pc = (r>>1)&1, v = r>>2: t = v%5, bg = v/5
    const int half = r & 1;
    const int pc   = (r >> 1) & 1;
    const int v    = r >> 2;
    const int t    = v % 5;
    const int bg   = v / 5;
    const int b    = bg >> 2;
    const int g    = bg & 3;
    const int tid  = threadIdx.x;
    const int og   = tid & 3;        // 8 outputs: og*8..og*8+7 (head slot n = og)
    const int pg   = tid >> 2;       // 72 groups x 4 px = 288 px

    // duplicated-weight smem: sm[c*64 + 2e + {0,1}] = w[e][c]
    for (int i = tid; i < CH*64; i += 288) {
        int c = i >> 6, ed = i & 63;
        sm[i] = kvw[(g*(DK+DV) + half*32 + (ed >> 1))*CH + c];
    }
    float* smb = sm + CH*64;
    if (tid < 32) smb[tid] = kvb[g*(DK+DV) + half*32 + tid];
    __syncthreads();

    ull acc[8][2];
    #pragma unroll
    for (int o = 0; o < 8; o++) { acc[o][0] = 0ull; acc[o][1] = 0ull; }

    const int pxbase = pc*288 + pg*4;
    const float* hb = hist + ((b*TT + t)*CH)*HWN + pxbase;

    #pragma unroll 4
    for (int c = 0; c < CH; c++) {
        ulonglong2 pp = *(const ulonglong2*)(hb + c*HWN);   // (px0,px1),(px2,px3)
        const ulonglong2* wd = (const ulonglong2*)(sm + c*64 + og*16);
        ulonglong2 wA = wd[0], wB = wd[1], wC = wd[2], wD = wd[3];
        ull wv[8] = {wA.x, wA.y, wB.x, wB.y, wC.x, wC.y, wD.x, wD.y};
        #pragma unroll
        for (int o = 0; o < 8; o++) {
            acc[o][0] = ffma2(wv[o], pp.x, acc[o][0]);
            acc[o][1] = ffma2(wv[o], pp.y, acc[o][1]);
        }
    }

    float av[8][4];
    #pragma unroll
    for (int o = 0; o < 8; o++) {
        float bb = smb[og*8 + o];
        unpack2(acc[o][0], av[o][0], av[o][1]);
        unpack2(acc[o][1], av[o][2], av[o][3]);
        #pragma unroll
        for (int p = 0; p < 4; p++) av[o][p] += bb;
    }

    const int head = (b*GG + g)*NHN + og;
    if (half == 0) {
        // K: write duplicated (k,k) pairs
        #pragma unroll
        for (int p = 0; p < 4; p++) {
            int j = t*HWN + pxbase + p;
            float4* dst = (float4*)&g_K2[(head*TKEYS + j)*16];
            dst[0] = make_float4(av[0][p], av[0][p], av[1][p], av[1][p]);
            dst[1] = make_float4(av[2][p], av[2][p], av[3][p], av[3][p]);
            dst[2] = make_float4(av[4][p], av[4][p], av[5][p], av[5][p]);
            dst[3] = make_float4(av[6][p], av[6][p], av[7][p], av[7][p]);
        }
    } else {
        #pragma unroll
        for (int p = 0; p < 4; p++) {
            int j = t*HWN + pxbase + p;
            g_V[(head*TKEYS + j)*2    ] = make_float4(av[0][p], av[1][p], av[2][p], av[3][p]);
            g_V[(head*TKEYS + j)*2 + 1] = make_float4(av[4][p], av[5][p], av[6][p], av[7][p]);
        }
    }
}

// ---- q body: 8 outputs x 2 px per thread, scale folds log2e ------------------
__device__ __forceinline__
void q_body(const float* __restrict__ rep,  // [B][CH][HW]
            const float* __restrict__ qw,   // [G][DK][CH]
            const float* __restrict__ qb,   // [G][DK]
            int r, float* sm)
{
    const int bg    = r >> 2;
    const int chunk = r & 3;         // 4 chunks of 144 px
    const int b     = bg >> 2;
    const int g     = bg & 3;
    const int tid   = threadIdx.x;
    const int og    = tid & 3;
    const int pg    = tid >> 2;      // 0..71
    const int px0   = chunk*144 + pg*2;

    for (int i = tid; i < CH*32; i += 288) {
        int e = i & 31, c = i >> 5;
        sm[c*32 + e] = qw[(g*DK + e)*CH + c];
    }
    float* smb = sm + CH*32;
    if (tid < 32) smb[tid] = qb[g*DK + tid];
    __syncthreads();

    float acc[8][2];
    #pragma unroll
    for (int o = 0; o < 8; o++) { acc[o][0] = 0.f; acc[o][1] = 0.f; }

    const float* rb = rep + (b*CH)*HWN + px0;
    #pragma unroll 4
    for (int c = 0; c < CH; c++) {
        float2 px = *(const float2*)(rb + c*HWN);
        float4 w0 = *(const float4*)(&sm[c*32 + og*8]);
        float4 w1 = *(const float4*)(&sm[c*32 + og*8 + 4]);
        float wv[8] = {w0.x, w0.y, w0.z, w0.w, w1.x, w1.y, w1.z, w1.w};
        #pragma unroll
        for (int o = 0; o < 8; o++) {
            acc[o][0] = fmaf(wv[o], px.x, acc[o][0]);
            acc[o][1] = fmaf(wv[o], px.y, acc[o][1]);
        }
    }

    const float scale = 0.51006972f;   // log2(e) / sqrt(8): softmax via exp2
    const int head = (b*GG + g)*NHN + og;
    float bb[8];
    #pragma unroll
    for (int o = 0; o < 8; o++) bb[o] = smb[og*8 + o];
    #pragma unroll
    for (int p = 0; p < 2; p++) {
        int hw = px0 + p;
        g_q[(head*HWN + hw)*2    ] = make_float4((acc[0][p]+bb[0])*scale, (acc[1][p]+bb[1])*scale,
                                                 (acc[2][p]+bb[2])*scale, (acc[3][p]+bb[3])*scale);
        g_q[(head*HWN + hw)*2 + 1] = make_float4((acc[4][p]+bb[4])*scale, (acc[5][p]+bb[5])*scale,
                                                 (acc[6][p]+bb[6])*scale, (acc[7][p]+bb[7])*scale);
    }
}

__global__ __launch_bounds__(288)
void front_kernel(const float* __restrict__ inputs,
                  const float* __restrict__ rep,
                  const float* __restrict__ history,
                  const float* __restrict__ Wx_w, const float* __restrict__ Wx_b,
                  const float* __restrict__ conv_w, const float* __restrict__ conv_b,
                  const float* __restrict__ q_w, const float* __restrict__ q_b,
                  const float* __restrict__ kv_w, const float* __restrict__ kv_b)
{
    __shared__ __align__(16) float sm[CH*64 + 64];   // 4160 floats, worst-case branch
    const int bid = blockIdx.x;
    if (bid < 128) {
        conv_body<CH, CH-DV, 1>(rep, conv_w, conv_b, bid, sm);          // heaviest first
    } else if (bid < 384) {
        conv_body<CIN, CH, 0>(inputs, Wx_w, Wx_b, bid - 128, sm);
    } else if (bid < 704) {
        kv_body(history, kv_w, kv_b, bid - 384, sm);
    } else {
        q_body(rep, q_w, q_b, bid - 704, sm);
    }
}

// =============================================================================
// Attention: f32x2. 2 queries/thread packed; K duplicated; exp2 softmax;
// linear partials over 8 key chunks (no max-subtraction: |logit| < ~2).
// =============================================================================
__global__ __launch_bounds__(288)
void attn_kernel()
{
    const int head = blockIdx.x;       // 0..63
    const int kc   = blockIdx.y;       // 0..7
    const int tid  = threadIdx.x;

    const int q0 = tid, q1 = tid + 288;

    const float* qf = (const float*)g_q;
    const float* Q0 = qf + (head*HWN + q0)*8;
    const float* Q1 = qf + (head*HWN + q1)*8;
    ull qp[8];
    #pragma unroll
    for (int d = 0; d < 8; d++) qp[d] = pack2(__ldg(Q0 + d), __ldg(Q1 + d));

    const ulonglong2* Kp = (const ulonglong2*)&g_K2[(head*TKEYS + kc*KPC)*16];
    const ulonglong2* Vp = (const ulonglong2*)(g_V + (head*TKEYS + kc*KPC)*2);

    float l0 = 0.f, l1 = 0.f;
    ull acc0[4], acc1[4];
    #pragma unroll
    for (int i = 0; i < 4; i++) { acc0[i] = 0ull; acc1[i] = 0ull; }

    #pragma unroll 2
    for (int j = 0; j < KPC; j++) {
        ulonglong2 ka = __ldg(Kp + j*4);
        ulonglong2 kb = __ldg(Kp + j*4 + 1);
        ulonglong2 kx = __ldg(Kp + j*4 + 2);
        ulonglong2 kd = __ldg(Kp + j*4 + 3);
        ull s = fmul2(qp[0], ka.x);
        s = ffma2(qp[1], ka.y, s);
        s = ffma2(qp[2], kb.x, s);
        s = ffma2(qp[3], kb.y, s);
        s = ffma2(qp[4], kx.x, s);
        s = ffma2(qp[5], kx.y, s);
        s = ffma2(qp[6], kd.x, s);
        s = ffma2(qp[7], kd.y, s);
        float s0, s1; unpack2(s, s0, s1);
        float p0 = ex2f(s0);
        float p1 = ex2f(s1);
        l0 += p0; l1 += p1;
        ull P0 = pack2(p0, p0), P1 = pack2(p1, p1);
        ulonglong2 va = __ldg(Vp + j*2);
        ulonglong2 vb = __ldg(Vp + j*2 + 1);
        acc0[0] = ffma2(P0, va.x, acc0[0]);
        acc0[1] = ffma2(P0, va.y, acc0[1]);
        acc0[2] = ffma2(P0, vb.x, acc0[2]);
        acc0[3] = ffma2(P0, vb.y, acc0[3]);
        acc1[0] = ffma2(P1, va.x, acc1[0]);
        acc1[1] = ffma2(P1, va.y, acc1[1]);
        acc1[2] = ffma2(P1, vb.x, acc1[2]);
        acc1[3] = ffma2(P1, vb.y, acc1[3]);
    }

    const int base = (kc*HEADS + head)*HWN;
    g_L[base + q0] = l0;
    g_L[base + q1] = l1;
    ulonglong2* d0 = (ulonglong2*)&g_A[(base + q0)*2];
    d0[0] = make_ulonglong2(acc0[0], acc0[1]);
    d0[1] = make_ulonglong2(acc0[2], acc0[3]);
    ulonglong2* d1 = (ulonglong2*)&g_A[(base + q1)*2];
    d1[0] = make_ulonglong2(acc1[0], acc1[1]);
    d1[1] = make_ulonglong2(acc1[2], acc1[3]);
}

// ---------------- combine partials + output projection ----------------------
__global__ __launch_bounds__(192)
void proj_kernel(const float* __restrict__ pw,  // [G][DV][DV]
                 const float* __restrict__ pb)  // [G][DV]
{
    const int b = blockIdx.x, g = blockIdx.y, hwc = blockIdx.z;
    const int tid = threadIdx.x;
    const int hw = hwc*192 + tid;

    __shared__ float ws[DV*DV];
    for (int i = tid; i < DV*DV; i += 192) ws[i] = pw[g*DV*DV + i];
    __syncthreads();

    float av[DV];
    #pragma unroll
    for (int n = 0; n < NHN; n++) {
        int head = (b*GG + g)*NHN + n;
        int qi = head*HWN + hw;
        float l = 0.f;
        float4 s0 = make_float4(0.f,0.f,0.f,0.f);
        float4 s1 = make_float4(0.f,0.f,0.f,0.f);
        #pragma unroll
        for (int kcc = 0; kcc < KC; kcc++) {
            int idx = kcc*HEADS*HWN + qi;
            l += g_L[idx];
            float4 t0 = g_A[idx*2], t1 = g_A[idx*2 + 1];
            s0.x += t0.x; s0.y += t0.y; s0.z += t0.z; s0.w += t0.w;
            s1.x += t1.x; s1.y += t1.y; s1.z += t1.z; s1.w += t1.w;
        }
        float inv = 1.f / l;
        av[n*8 + 0] = s0.x*inv; av[n*8 + 1] = s0.y*inv;
        av[n*8 + 2] = s0.z*inv; av[n*8 + 3] = s0.w*inv;
        av[n*8 + 4] = s1.x*inv; av[n*8 + 5] = s1.y*inv;
        av[n*8 + 6] = s1.z*inv; av[n*8 + 7] = s1.w*inv;
    }

    #pragma unroll 4
    for (int dout = 0; dout < DV; dout++) {
        float o = __ldg(pb + g*DV + dout);
        #pragma unroll
        for (int di = 0; di < DV; di++) o = fmaf(av[di], ws[dout*DV + di], o);
        g_attnp[((b*GG + g)*DV + dout)*HWN + hw] = o;
    }
}

// ---------------- LSTM gates ------------------------------------------------
__device__ __forceinline__ float sigmf(float x) { return 1.f / (1.f + __expf(-x)); }

__global__ __launch_bounds__(576)
void gates_kernel(const float* __restrict__ c_in,
                  const float* __restrict__ Wci,
                  const float* __restrict__ Wcf,
                  const float* __restrict__ Wco,
                  float* __restrict__ out)
{
    const int b  = blockIdx.x >> 6;
    const int ch = blockIdx.x & 63;
    const int hw = threadIdx.x;

    float pre[GG];
    #pragma unroll
    for (int g = 0; g < GG; g++) {
        float x = g_xg[((b*GG + g)*CH + ch)*HWN + hw];
        float y = (ch < 32) ? g_co[((b*GG + g)*(CH-DV) + ch)*HWN + hw]
                            : g_attnp[((b*GG + g)*DV + (ch - 32))*HWN + hw];
        pre[g] = x + y;
    }

    float c  = __ldg(c_in + (b*CH + ch)*HWN + hw);
    float ci = __ldg(Wci + ch*HWN + hw);
    float cf = __ldg(Wcf + ch*HWN + hw);
    float co = __ldg(Wco + ch*HWN + hw);

    float i_t = sigmf(pre[0] + c*ci);
    float f_t = sigmf(pre[1] + c*cf + 1.0f);
    float c_t = f_t*c + i_t*tanhf(pre[2]);
    float o_t = sigmf(pre[3] + c_t*co);
    float h_t = o_t*tanhf(c_t);

    const int idx = (b*CH + ch)*HWN + hw;
    out[idx] = h_t;
    out[BB*CH*HWN + idx] = c_t;
}

// ---------------- launcher ---------------------------------------------------
extern "C" void kernel_launch(void* const* d_in, const int* in_sizes, int n_in,
                              void* d_out, int out_size)
{
    const float* inputs  = (const float*)d_in[0];
    const float* rep     = (const float*)d_in[1];
    const float* c_in    = (const float*)d_in[2];
    const float* history = (const float*)d_in[3];
    const float* Wx_w    = (const float*)d_in[4];
    const float* Wx_b    = (const float*)d_in[5];
    const float* conv_w  = (const float*)d_in[6];
    const float* conv_b  = (const float*)d_in[7];
    const float* q_w     = (const float*)d_in[8];
    const float* q_b     = (const float*)d_in[9];
    const float* kv_w    = (const float*)d_in[10];
    const float* kv_b    = (const float*)d_in[11];
    const float* proj_w  = (const float*)d_in[12];
    const float* proj_b  = (const float*)d_in[13];
    const float* Wci     = (const float*)d_in[14];
    const float* Wcf     = (const float*)d_in[15];
    const float* Wco     = (const float*)d_in[16];
    float* out = (float*)d_out;
    (void)in_sizes; (void)n_in; (void)out_size;

    // all independent pre-attention work in one fat launch
    front_kernel<<<768, 288>>>(inputs, rep, history,
                               Wx_w, Wx_b, conv_w, conv_b,
                               q_w, q_b, kv_w, kv_b);
    // attention partials (8 key chunks)
    attn_kernel<<<dim3(HEADS, KC), 288>>>();
    // combine + projection
    proj_kernel<<<dim3(BB, GG, 3), 192>>>(proj_w, proj_b);
    // LSTM gates -> h_t, c_t
    gates_kernel<<<BB*CH, HWN>>>(c_in, Wci, Wcf, Wco, out);
}

// round 6
// speedup vs baseline: 1.6030x; 1.6030x over previous
#include <cuda_runtime.h>
#include <math.h>

// Problem constants
#define BB   4
#define CIN  32
#define CH   64
#define HH   24
#define WW   24
#define HWN  576          // 24*24
#define TT   5
#define DK   32
#define DV   32
#define NHN  4
#define GG   4
#define HEADS 64          // B*G*NH
#define TKEYS 2880        // T*HW
#define KC    9           // key chunks
#define KPC   320         // keys per chunk
#define ATTN_THREADS 192  // 3 queries per thread

// ---------------- scratch (device globals; no allocation allowed) -------------
__device__ float  g_xg[BB*GG*CH*HWN];        // conv on inputs, 4 gates x 64 ch
__device__ float  g_co[BB*GG*(CH-DV)*HWN];   // conv on rep, 4 gates x 32 ch
__device__ float4 g_q[HEADS*HWN*2];          // Q [head][q][8] (scaled by log2e/sqrt8)
__device__ float4 g_K[HEADS*TKEYS*2];        // K [head][j][8]
__device__ float4 g_V[HEADS*TKEYS*2];        // V [head][j][8]
__device__ float  g_L[KC*HEADS*HWN];         // partial exp-sums
__device__ float4 g_A[KC*HEADS*HWN*2];       // partial weighted V sums
__device__ float  g_attnp[BB*GG*DV*HWN];     // projected attention

__device__ __forceinline__ float ex2f(float x) {
    float r; asm("ex2.approx.ftz.f32 %0,%1;" : "=f"(r) : "f"(x)); return r;
}

// ---------------- conv: 4 gates per thread, 2 pixels per thread --------------
template<int IC, int OC, int WHICH>
__global__ __launch_bounds__(288)
void conv4g_kernel(const float* __restrict__ in,   // [B][IC][24][24]
                   const float* __restrict__ w,    // [G][OC][IC][3][3]
                   const float* __restrict__ bias) // [G][OC]
{
    const int oc = blockIdx.x;
    const int b  = blockIdx.y;
    const int tid = threadIdx.x;

    __shared__ float ws[GG*IC*9];
    for (int i = tid; i < GG*IC*9; i += 288) {
        int g = i / (IC*9);
        int r = i - g*(IC*9);
        ws[i] = w[(g*OC + oc)*IC*9 + r];
    }
    __syncthreads();

    const int p0 = tid, p1 = tid + 288;
    const int y0 = p0 / WW, x0 = p0 % WW;
    const int y1 = p1 / WW, x1 = p1 % WW;

    float acc0[GG], acc1[GG];
    #pragma unroll
    for (int g = 0; g < GG; g++) {
        float bv = __ldg(bias + g*OC + oc);
        acc0[g] = bv; acc1[g] = bv;
    }

    for (int ic = 0; ic < IC; ic++) {
        const float* ip = in + (b*IC + ic)*HWN;
        float v0[9], v1[9];
        #pragma unroll
        for (int ky = 0; ky < 3; ky++) {
            #pragma unroll
            for (int kx = 0; kx < 3; kx++) {
                int iy = y0 + ky - 1, ix = x0 + kx - 1;
                v0[ky*3+kx] = (iy >= 0 && iy < HH && ix >= 0 && ix < WW)
                              ? __ldg(ip + iy*WW + ix) : 0.f;
                int jy = y1 + ky - 1, jx = x1 + kx - 1;
                v1[ky*3+kx] = (jy >= 0 && jy < HH && jx >= 0 && jx < WW)
                              ? __ldg(ip + jy*WW + jx) : 0.f;
            }
        }
        #pragma unroll
        for (int g = 0; g < GG; g++) {
            const float* wp = &ws[(g*IC + ic)*9];
            #pragma unroll
            for (int kk = 0; kk < 9; kk++) {
                float wv = wp[kk];
                acc0[g] = fmaf(v0[kk], wv, acc0[g]);
                acc1[g] = fmaf(v1[kk], wv, acc1[g]);
            }
        }
    }
    float* out = (WHICH == 0) ? g_xg : g_co;
    #pragma unroll
    for (int g = 0; g < GG; g++) {
        out[((b*GG + g)*OC + oc)*HWN + p0] = acc0[g];
        out[((b*GG + g)*OC + oc)*HWN + p1] = acc1[g];
    }
}

// ---------------- KV projection, register-tiled, 288-thread blocks ------------
// grid: x = t*2 + pixel-chunk (10), y = b*G+g (16), z = half (2) -> 320 blocks.
// Thread: og = tid&3 (8 outputs, head slot n == og), pg = tid>>2 (4 pixels).
// Per c-step: 1 LDG.128 + 2 LDS.128 -> 32 FMA.
__global__ __launch_bounds__(288)
void kv_tiled_kernel(const float* __restrict__ hist, // [B][T][CH][HW]
                     const float* __restrict__ kvw,  // [G][DK+DV][CH]
                     const float* __restrict__ kvb)  // [G][DK+DV]
{
    const int t    = blockIdx.x >> 1;
    const int pc   = blockIdx.x & 1;
    const int b    = blockIdx.y >> 2;
    const int g    = blockIdx.y & 3;
    const int half = blockIdx.z;
    const int tid  = threadIdx.x;
    const int og   = tid & 3;
    const int pg   = tid >> 2;          // 0..71

    __shared__ float wt[CH*32];         // [c][e] transposed
    __shared__ float bs[32];
    for (int i = tid; i < CH*32; i += 288) {
        int e = i & 31, c = i >> 5;
        wt[c*32 + e] = kvw[(g*(DK+DV) + half*32 + e)*CH + c];
    }
    if (tid < 32) bs[tid] = kvb[g*(DK+DV) + half*32 + tid];
    __syncthreads();

    float acc[8][4];
    #pragma unroll
    for (int o = 0; o < 8; o++)
        #pragma unroll
        for (int p = 0; p < 4; p++) acc[o][p] = 0.f;

    const int pxbase = pc*288 + pg*4;
    const float* hb = hist + ((b*TT + t)*CH)*HWN + pxbase;
    #pragma unroll 4
    for (int c = 0; c < CH; c++) {
        float4 px = *(const float4*)(hb + c*HWN);
        float4 w0 = *(const float4*)(&wt[c*32 + og*8]);
        float4 w1 = *(const float4*)(&wt[c*32 + og*8 + 4]);
        float wv[8] = {w0.x, w0.y, w0.z, w0.w, w1.x, w1.y, w1.z, w1.w};
        float pv[4] = {px.x, px.y, px.z, px.w};
        #pragma unroll
        for (int o = 0; o < 8; o++)
            #pragma unroll
            for (int p = 0; p < 4; p++)
                acc[o][p] = fmaf(wv[o], pv[p], acc[o][p]);
    }

    const int head = (b*GG + g)*NHN + og;
    float4* dst = (half == 0) ? g_K : g_V;
    float bb[8];
    #pragma unroll
    for (int o = 0; o < 8; o++) bb[o] = bs[og*8 + o];
    #pragma unroll
    for (int p = 0; p < 4; p++) {
        int j = t*HWN + pxbase + p;
        dst[(head*TKEYS + j)*2    ] = make_float4(acc[0][p]+bb[0], acc[1][p]+bb[1],
                                                  acc[2][p]+bb[2], acc[3][p]+bb[3]);
        dst[(head*TKEYS + j)*2 + 1] = make_float4(acc[4][p]+bb[4], acc[5][p]+bb[5],
                                                  acc[6][p]+bb[6], acc[7][p]+bb[7]);
    }
}

// ---------------- Q projection, 288-thread blocks, scale folds log2e ---------
__global__ __launch_bounds__(288)
void q_tiled_kernel(const float* __restrict__ rep,  // [B][CH][HW]
                    const float* __restrict__ qw,   // [G][DK][CH]
                    const float* __restrict__ qb)   // [G][DK]
{
    const int b     = blockIdx.x >> 2;
    const int g     = blockIdx.x & 3;
    const int chunk = blockIdx.y;       // 4 chunks of 144 px
    const int tid   = threadIdx.x;
    const int og    = tid & 3;
    const int pg    = tid >> 2;         // 0..71
    const int px0   = chunk*144 + pg*2;

    __shared__ float wt[CH*32];
    __shared__ float bs[32];
    for (int i = tid; i < CH*32; i += 288) {
        int e = i & 31, c = i >> 5;
        wt[c*32 + e] = qw[(g*DK + e)*CH + c];
    }
    if (tid < 32) bs[tid] = qb[g*DK + tid];
    __syncthreads();

    float acc[8][2];
    #pragma unroll
    for (int o = 0; o < 8; o++) { acc[o][0] = 0.f; acc[o][1] = 0.f; }

    const float* rb = rep + (b*CH)*HWN + px0;
    #pragma unroll 4
    for (int c = 0; c < CH; c++) {
        float2 px = *(const float2*)(rb + c*HWN);
        float4 w0 = *(const float4*)(&wt[c*32 + og*8]);
        float4 w1 = *(const float4*)(&wt[c*32 + og*8 + 4]);
        float wv[8] = {w0.x, w0.y, w0.z, w0.w, w1.x, w1.y, w1.z, w1.w};
        #pragma unroll
        for (int o = 0; o < 8; o++) {
            acc[o][0] = fmaf(wv[o], px.x, acc[o][0]);
            acc[o][1] = fmaf(wv[o], px.y, acc[o][1]);
        }
    }

    const float scale = 0.51006972f;    // log2(e) / sqrt(8): softmax via ex2
    const int head = (b*GG + g)*NHN + og;
    float bb[8];
    #pragma unroll
    for (int o = 0; o < 8; o++) bb[o] = bs[og*8 + o];
    #pragma unroll
    for (int p = 0; p < 2; p++) {
        int hw = px0 + p;
        g_q[(head*HWN + hw)*2    ] = make_float4((acc[0][p]+bb[0])*scale, (acc[1][p]+bb[1])*scale,
                                                 (acc[2][p]+bb[2])*scale, (acc[3][p]+bb[3])*scale);
        g_q[(head*HWN + hw)*2 + 1] = make_float4((acc[4][p]+bb[4])*scale, (acc[5][p]+bb[5])*scale,
                                                 (acc[6][p]+bb[6])*scale, (acc[7][p]+bb[7])*scale);
    }
}

// ---------------- attention: 3 queries/thread, ex2 softmax, no max -----------
__global__ __launch_bounds__(ATTN_THREADS)
void attn_kernel()
{
    const int head = blockIdx.x;       // 0..63
    const int kc   = blockIdx.y;       // 0..8
    const int tid  = threadIdx.x;

    const int q0 = tid, q1 = tid + 192, q2 = tid + 384;

    const float4* Qp = g_q + head*HWN*2;
    float4 qA0 = __ldg(Qp + q0*2), qB0 = __ldg(Qp + q0*2 + 1);
    float4 qA1 = __ldg(Qp + q1*2), qB1 = __ldg(Qp + q1*2 + 1);
    float4 qA2 = __ldg(Qp + q2*2), qB2 = __ldg(Qp + q2*2 + 1);

    const float4* Kp = g_K + (head*TKEYS + kc*KPC)*2;
    const float4* Vp = g_V + (head*TKEYS + kc*KPC)*2;

    float l0 = 0.f, l1 = 0.f, l2 = 0.f;
    float a0[8], a1[8], a2[8];
    #pragma unroll
    for (int d = 0; d < 8; d++) { a0[d]=0.f; a1[d]=0.f; a2[d]=0.f; }

    #pragma unroll 2
    for (int j = 0; j < KPC; j++) {
        float4 ka = __ldg(Kp + j*2);
        float4 kb = __ldg(Kp + j*2 + 1);
        float s0 = qA0.x*ka.x + qA0.y*ka.y + qA0.z*ka.z + qA0.w*ka.w
                 + qB0.x*kb.x + qB0.y*kb.y + qB0.z*kb.z + qB0.w*kb.w;
        float s1 = qA1.x*ka.x + qA1.y*ka.y + qA1.z*ka.z + qA1.w*ka.w
                 + qB1.x*kb.x + qB1.y*kb.y + qB1.z*kb.z + qB1.w*kb.w;
        float s2 = qA2.x*ka.x + qA2.y*ka.y + qA2.z*ka.z + qA2.w*ka.w
                 + qB2.x*kb.x + qB2.y*kb.y + qB2.z*kb.z + qB2.w*kb.w;
        float p0 = ex2f(s0);      // Q pre-scaled by log2e -> true exp
        float p1 = ex2f(s1);
        float p2 = ex2f(s2);
        l0 += p0; l1 += p1; l2 += p2;
        float4 va = __ldg(Vp + j*2);
        float4 vb = __ldg(Vp + j*2 + 1);
        a0[0]=fmaf(p0,va.x,a0[0]); a0[1]=fmaf(p0,va.y,a0[1]); a0[2]=fmaf(p0,va.z,a0[2]); a0[3]=fmaf(p0,va.w,a0[3]);
        a0[4]=fmaf(p0,vb.x,a0[4]); a0[5]=fmaf(p0,vb.y,a0[5]); a0[6]=fmaf(p0,vb.z,a0[6]); a0[7]=fmaf(p0,vb.w,a0[7]);
        a1[0]=fmaf(p1,va.x,a1[0]); a1[1]=fmaf(p1,va.y,a1[1]); a1[2]=fmaf(p1,va.z,a1[2]); a1[3]=fmaf(p1,va.w,a1[3]);
        a1[4]=fmaf(p1,vb.x,a1[4]); a1[5]=fmaf(p1,vb.y,a1[5]); a1[6]=fmaf(p1,vb.z,a1[6]); a1[7]=fmaf(p1,vb.w,a1[7]);
        a2[0]=fmaf(p2,va.x,a2[0]); a2[1]=fmaf(p2,va.y,a2[1]); a2[2]=fmaf(p2,va.z,a2[2]); a2[3]=fmaf(p2,va.w,a2[3]);
        a2[4]=fmaf(p2,vb.x,a2[4]); a2[5]=fmaf(p2,vb.y,a2[5]); a2[6]=fmaf(p2,vb.z,a2[6]); a2[7]=fmaf(p2,vb.w,a2[7]);
    }

    const int base = (kc*HEADS + head)*HWN;
    g_L[base + q0] = l0;
    g_L[base + q1] = l1;
    g_L[base + q2] = l2;
    g_A[(base + q0)*2    ] = make_float4(a0[0], a0[1], a0[2], a0[3]);
    g_A[(base + q0)*2 + 1] = make_float4(a0[4], a0[5], a0[6], a0[7]);
    g_A[(base + q1)*2    ] = make_float4(a1[0], a1[1], a1[2], a1[3]);
    g_A[(base + q1)*2 + 1] = make_float4(a1[4], a1[5], a1[6], a1[7]);
    g_A[(base + q2)*2    ] = make_float4(a2[0], a2[1], a2[2], a2[3]);
    g_A[(base + q2)*2 + 1] = make_float4(a2[4], a2[5], a2[6], a2[7]);
}

// ---------------- combine partials + output projection ----------------------
__global__ __launch_bounds__(192)
void proj_kernel(const float* __restrict__ pw,  // [G][DV][DV]
                 const float* __restrict__ pb)  // [G][DV]
{
    const int b = blockIdx.x, g = blockIdx.y, hwc = blockIdx.z;
    const int tid = threadIdx.x;
    const int hw = hwc*192 + tid;

    __shared__ float ws[DV*DV];
    for (int i = tid; i < DV*DV; i += 192) ws[i] = pw[g*DV*DV + i];
    __syncthreads();

    float av[DV];
    #pragma unroll
    for (int n = 0; n < NHN; n++) {
        int head = (b*GG + g)*NHN + n;
        int qi = head*HWN + hw;
        float l = 0.f;
        float4 s0 = make_float4(0.f,0.f,0.f,0.f);
        float4 s1 = make_float4(0.f,0.f,0.f,0.f);
        #pragma unroll
        for (int kcc = 0; kcc < KC; kcc++) {
            int idx = kcc*HEADS*HWN + qi;
            l += g_L[idx];
            float4 t0 = g_A[idx*2], t1 = g_A[idx*2 + 1];
            s0.x += t0.x; s0.y += t0.y; s0.z += t0.z; s0.w += t0.w;
            s1.x += t1.x; s1.y += t1.y; s1.z += t1.z; s1.w += t1.w;
        }
        float inv = 1.f / l;
        av[n*8 + 0] = s0.x*inv; av[n*8 + 1] = s0.y*inv;
        av[n*8 + 2] = s0.z*inv; av[n*8 + 3] = s0.w*inv;
        av[n*8 + 4] = s1.x*inv; av[n*8 + 5] = s1.y*inv;
        av[n*8 + 6] = s1.z*inv; av[n*8 + 7] = s1.w*inv;
    }

    #pragma unroll 4
    for (int dout = 0; dout < DV; dout++) {
        float o = __ldg(pb + g*DV + dout);
        #pragma unroll
        for (int di = 0; di < DV; di++) o = fmaf(av[di], ws[dout*DV + di], o);
        g_attnp[((b*GG + g)*DV + dout)*HWN + hw] = o;
    }
}

// ---------------- LSTM gates ------------------------------------------------
__device__ __forceinline__ float sigmf(float x) { return 1.f / (1.f + __expf(-x)); }

__global__ __launch_bounds__(576)
void gates_kernel(const float* __restrict__ c_in,
                  const float* __restrict__ Wci,
                  const float* __restrict__ Wcf,
                  const float* __restrict__ Wco,
                  float* __restrict__ out)
{
    const int b  = blockIdx.x >> 6;
    const int ch = blockIdx.x & 63;
    const int hw = threadIdx.x;

    float pre[GG];
    #pragma unroll
    for (int g = 0; g < GG; g++) {
        float x = g_xg[((b*GG + g)*CH + ch)*HWN + hw];
        float y = (ch < 32) ? g_co[((b*GG + g)*(CH-DV) + ch)*HWN + hw]
                            : g_attnp[((b*GG + g)*DV + (ch - 32))*HWN + hw];
        pre[g] = x + y;
    }

    float c  = __ldg(c_in + (b*CH + ch)*HWN + hw);
    float ci = __ldg(Wci + ch*HWN + hw);
    float cf = __ldg(Wcf + ch*HWN + hw);
    float co = __ldg(Wco + ch*HWN + hw);

    float i_t = sigmf(pre[0] + c*ci);
    float f_t = sigmf(pre[1] + c*cf + 1.0f);
    float c_t = f_t*c + i_t*tanhf(pre[2]);
    float o_t = sigmf(pre[3] + c_t*co);
    float h_t = o_t*tanhf(c_t);

    const int idx = (b*CH + ch)*HWN + hw;
    out[idx] = h_t;
    out[BB*CH*HWN + idx] = c_t;
}

// ---------------- launcher ---------------------------------------------------
extern "C" void kernel_launch(void* const* d_in, const int* in_sizes, int n_in,
                              void* d_out, int out_size)
{
    const float* inputs  = (const float*)d_in[0];
    const float* rep     = (const float*)d_in[1];
    const float* c_in    = (const float*)d_in[2];
    const float* history = (const float*)d_in[3];
    const float* Wx_w    = (const float*)d_in[4];
    const float* Wx_b    = (const float*)d_in[5];
    const float* conv_w  = (const float*)d_in[6];
    const float* conv_b  = (const float*)d_in[7];
    const float* q_w     = (const float*)d_in[8];
    const float* q_b     = (const float*)d_in[9];
    const float* kv_w    = (const float*)d_in[10];
    const float* kv_b    = (const float*)d_in[11];
    const float* proj_w  = (const float*)d_in[12];
    const float* proj_b  = (const float*)d_in[13];
    const float* Wci     = (const float*)d_in[14];
    const float* Wcf     = (const float*)d_in[15];
    const float* Wco     = (const float*)d_in[16];
    float* out = (float*)d_out;
    (void)in_sizes; (void)n_in; (void)out_size;

    // convs
    conv4g_kernel<CIN, CH, 0><<<dim3(CH, BB), 288>>>(inputs, Wx_w, Wx_b);
    conv4g_kernel<CH, CH-DV, 1><<<dim3(CH-DV, BB), 288>>>(rep, conv_w, conv_b);
    // projections
    q_tiled_kernel<<<dim3(BB*GG, 4), 288>>>(rep, q_w, q_b);
    kv_tiled_kernel<<<dim3(TT*2, BB*GG, 2), 288>>>(history, kv_w, kv_b);
    // attention (partials over 9 key chunks)
    attn_kernel<<<dim3(HEADS, KC), ATTN_THREADS>>>();
    // combine + projection
    proj_kernel<<<dim3(BB, GG, 3), 192>>>(proj_w, proj_b);
    // LSTM gates -> h_t, c_t
    gates_kernel<<<BB*CH, HWN>>>(c_in, Wci, Wcf, Wco, out);
}